// round 11
// baseline (speedup 1.0000x reference)
#include <cuda_runtime.h>

#define NMAX 100000
#define EMAX 3200000
#define FIN  512
#define HID  16
#define SCAN_BS 1024
#define SCAN_NBMAX 128
#define ROWS_A 50176            // 196 blocks x 256 rows

// ---------------- scratch (zero-initialized at module load) ----------------
__device__ int   d_cnt [NMAX];          // per-dst edge count (re-zeroed in scanFix)
__device__ float d_dinv[NMAX];          // (deg+1)^-1/2
__device__ float d_h1p [NMAX * HID];    // h1 (raw), then h1*dinv after scaledinv
__device__ float d_gp  [NMAX];          // g * dinv[row]
__device__ int   d_rs  [NMAX + 1];      // CSR row starts + sentinel
__device__ int   d_next[NMAX];          // fill cursors
__device__ int   d_csr [EMAX];          // src ids grouped by dst
__device__ int   d_bsum[SCAN_NBMAX];

__device__ __forceinline__ unsigned smem_u32(const void* p) {
    unsigned r;
    asm("{ .reg .u64 t; cvta.to.shared.u64 t, %1; cvt.u32.u64 %0, t; }"
        : "=r"(r) : "l"(p));
    return r;
}

// prefetch one 256-row x 32-col tile into smem via cp.async (XOR swizzle)
__device__ __forceinline__ void tile_prefetch(const float* __restrict__ x,
                                              unsigned bufbase, int rbase,
                                              int kt, int tid, int N) {
    #pragma unroll
    for (int i = 0; i < 16; i++) {
        int fid = tid + i * 128;
        int r = fid >> 3, c4 = fid & 7;
        int gr = rbase + r;
        if (gr < N) {
            const float* g = x + (size_t)gr * FIN + kt * 32 + c4 * 4;
            unsigned d = bufbase + (unsigned)((r * 8 + (c4 ^ (r & 7))) * 16);
            asm volatile("cp.async.cg.shared.global [%0], [%1], 16;"
                         :: "r"(d), "l"(g));
        }
    }
    asm volatile("cp.async.commit_group;");
}

// gemm mainloop for 256 rows starting at rbase (threads 0-127, 2 rows each).
__device__ __forceinline__ void gemm_body(const float* __restrict__ x,
                                          const float* __restrict__ W1,
                                          float* Ws, float* xs,
                                          int rbase, int tid, int N) {
    {   // stage W1
        const float4* W4 = (const float4*)W1;
        float4*       Wd = (float4*)Ws;
        #pragma unroll
        for (int i = 0; i < 16; i++)
            Wd[tid + i * 128] = W4[tid + i * 128];
    }
    unsigned buf0 = smem_u32(xs);
    unsigned long long a0[8], a1[8];
    #pragma unroll
    for (int j = 0; j < 8; j++) { a0[j] = 0ull; a1[j] = 0ull; }

    tile_prefetch(x, buf0, rbase, 0, tid, N);

    #pragma unroll 1
    for (int kt = 0; kt < 16; kt++) {
        if (kt < 15) {
            tile_prefetch(x, buf0 + ((kt + 1) & 1) * 32768, rbase, kt + 1, tid, N);
            asm volatile("cp.async.wait_group 1;");
        } else {
            asm volatile("cp.async.wait_group 0;");
        }
        asm volatile("bar.sync 1, 128;");

        const float4* xb = (const float4*)(xs + (kt & 1) * 8192);
        #pragma unroll
        for (int c4 = 0; c4 < 8; c4++) {
            int swz = c4 ^ (tid & 7);
            float4 X0 = xb[tid * 8 + swz];
            float4 X1 = xb[(tid + 128) * 8 + swz];
            #pragma unroll
            for (int cc = 0; cc < 4; cc++) {
                float f0 = (&X0.x)[cc], f1 = (&X1.x)[cc];
                unsigned long long s0, s1;
                asm("mov.b64 %0,{%1,%1};" : "=l"(s0) : "f"(f0));
                asm("mov.b64 %0,{%1,%1};" : "=l"(s1) : "f"(f1));
                const ulonglong2* wp =
                    (const ulonglong2*)(Ws + ((kt * 32 + c4 * 4 + cc) << 4));
                #pragma unroll
                for (int j = 0; j < 4; j++) {
                    ulonglong2 w = wp[j];
                    asm("fma.rn.f32x2 %0,%1,%2,%0;" : "+l"(a0[2*j])   : "l"(s0), "l"(w.x));
                    asm("fma.rn.f32x2 %0,%1,%2,%0;" : "+l"(a0[2*j+1]) : "l"(s0), "l"(w.y));
                    asm("fma.rn.f32x2 %0,%1,%2,%0;" : "+l"(a1[2*j])   : "l"(s1), "l"(w.x));
                    asm("fma.rn.f32x2 %0,%1,%2,%0;" : "+l"(a1[2*j+1]) : "l"(s1), "l"(w.y));
                }
            }
        }
        asm volatile("bar.sync 1, 128;");
    }

    int r0 = rbase + tid, r1 = r0 + 128;
    if (r0 < N) {
        float* hp = d_h1p + (size_t)r0 * HID;
        #pragma unroll
        for (int j = 0; j < 8; j++)
            asm("mov.b64 {%0,%1},%2;" : "=f"(hp[2*j]), "=f"(hp[2*j+1]) : "l"(a0[j]));
    }
    if (r1 < N) {
        float* hp = d_h1p + (size_t)r1 * HID;
        #pragma unroll
        for (int j = 0; j < 8; j++)
            asm("mov.b64 {%0,%1},%2;" : "=f"(hp[2*j]), "=f"(hp[2*j+1]) : "l"(a1[j]));
    }
}

// Phase A: gemm rows [0, ROWS_A) + degree histogram in sibling warps.
__global__ void __launch_bounds__(256) k_gemmA(const float* __restrict__ x,
                                               const float* __restrict__ W1,
                                               const int* __restrict__ dst,
                                               int N, int E) {
    extern __shared__ float sm[];
    int tid = threadIdx.x;
    if (tid >= 128) {                    // deg warps: fire-and-forget REDG
        int dt = tid - 128;
        long long start = (long long)blockIdx.x * E / gridDim.x;
        long long stop  = (long long)(blockIdx.x + 1) * E / gridDim.x;
        for (long long e = start + dt; e < stop; e += 128)
            atomicAdd(&d_cnt[dst[e]], 1);
        return;
    }
    gemm_body(x, W1, sm, sm + FIN * HID, blockIdx.x * 256, tid, N);
}

// Phase B: gemm rows [ROWS_A, N) + CSR fill (MLP=8) in sibling warps.
__global__ void __launch_bounds__(256) k_gemmB(const float* __restrict__ x,
                                               const float* __restrict__ W1,
                                               const int* __restrict__ ei,
                                               int N, int E) {
    extern __shared__ float sm[];
    int tid = threadIdx.x;
    if (tid >= 128) {                    // fill warps: 8 independent edges/round
        int ft = blockIdx.x * 128 + (tid - 128);
        int FT = gridDim.x * 128;
        int e8 = (E / 8) * 8;
        for (long long b = (long long)ft * 8; b < e8; b += (long long)FT * 8) {
            int4 sa = __ldg((const int4*)(ei + b));
            int4 sb = __ldg((const int4*)(ei + b + 4));
            int4 da = __ldg((const int4*)(ei + E + b));
            int4 db = __ldg((const int4*)(ei + E + b + 4));
            int i0 = atomicAdd(&d_next[da.x], 1);
            int i1 = atomicAdd(&d_next[da.y], 1);
            int i2 = atomicAdd(&d_next[da.z], 1);
            int i3 = atomicAdd(&d_next[da.w], 1);
            int i4 = atomicAdd(&d_next[db.x], 1);
            int i5 = atomicAdd(&d_next[db.y], 1);
            int i6 = atomicAdd(&d_next[db.z], 1);
            int i7 = atomicAdd(&d_next[db.w], 1);
            d_csr[i0] = sa.x; d_csr[i1] = sa.y; d_csr[i2] = sa.z; d_csr[i3] = sa.w;
            d_csr[i4] = sb.x; d_csr[i5] = sb.y; d_csr[i6] = sb.z; d_csr[i7] = sb.w;
        }
        if (ft == 0) {
            for (int e = e8; e < E; e++)
                d_csr[atomicAdd(&d_next[__ldg(ei + E + e)], 1)] = __ldg(ei + e);
        }
        return;
    }
    gemm_body(x, W1, sm, sm + FIN * HID, ROWS_A + blockIdx.x * 256, tid, N);
}

// ---------------- scan ----------------
__global__ void __launch_bounds__(SCAN_BS) k_scanA(int N) {
    int i = blockIdx.x * SCAN_BS + threadIdx.x;
    int lane = threadIdx.x & 31, w = threadIdx.x >> 5;
    int c = (i < N) ? d_cnt[i] : 0;
    int v = c;
    #pragma unroll
    for (int off = 1; off < 32; off <<= 1) {
        int n = __shfl_up_sync(0xffffffffu, v, off);
        if (lane >= off) v += n;
    }
    __shared__ int ws[32];
    if (lane == 31) ws[w] = v;
    __syncthreads();
    if (w == 0) {
        int s = ws[lane];
        #pragma unroll
        for (int off = 1; off < 32; off <<= 1) {
            int n = __shfl_up_sync(0xffffffffu, s, off);
            if (lane >= off) s += n;
        }
        ws[lane] = s;
    }
    __syncthreads();
    int add = w ? ws[w - 1] : 0;
    if (i < N) d_rs[i] = add + v - c;
    if (threadIdx.x == SCAN_BS - 1) d_bsum[blockIdx.x] = add + v;
}

__global__ void __launch_bounds__(256) k_scanFix(int N) {
    __shared__ int wsum[8];
    __shared__ int s_off;
    int t = threadIdx.x;
    int nb = blockIdx.x >> 2;
    int v = (t < nb && t < SCAN_NBMAX) ? d_bsum[t] : 0;
    #pragma unroll
    for (int off = 16; off >= 1; off >>= 1)
        v += __shfl_down_sync(0xffffffffu, v, off);
    if ((t & 31) == 0) wsum[t >> 5] = v;
    __syncthreads();
    if (t == 0) {
        int s = 0;
        #pragma unroll
        for (int k = 0; k < 8; k++) s += wsum[k];
        s_off = s;
    }
    __syncthreads();
    int i = blockIdx.x * 256 + t;
    if (i < N) {
        int c = d_cnt[i];
        int r = d_rs[i] + s_off;
        d_rs[i]   = r;
        d_next[i] = r;
        d_dinv[i] = rsqrtf((float)(c + 1));
        if (i == N - 1) d_rs[N] = r + c;
        d_cnt[i] = 0;
    }
}

// h1p *= dinv[row] (in place; messages become pre-scaled)
__global__ void k_scaledinv(int N4) {
    int t = blockIdx.x * blockDim.x + threadIdx.x;
    if (t >= N4) return;
    float dv = d_dinv[t >> 2];
    float4 v = ((float4*)d_h1p)[t];
    v.x *= dv; v.y *= dv; v.z *= dv; v.w *= dv;
    ((float4*)d_h1p)[t] = v;
}

// Layer-1 aggregation + fused layer-2 MLP. One warp per node, gather-only.
__global__ void __launch_bounds__(256) k_agg1(const float* __restrict__ b1,
                                              const float* __restrict__ W2,
                                              int N) {
    int warp = (blockIdx.x * blockDim.x + threadIdx.x) >> 5;
    if (warp >= N) return;
    int lane = threadIdx.x & 31;
    int p = lane & 3;
    int base = __ldg(&d_rs[warp]);
    int end  = __ldg(&d_rs[warp + 1]);

    float4 acc = make_float4(0.f, 0.f, 0.f, 0.f);
    int it = base + (lane >> 2);
    bool ok = it < end;
    int s = ok ? __ldg(&d_csr[it]) : 0;
    while (ok) {
        int it1 = it + 8;
        bool ok1 = it1 < end;
        int s1 = ok1 ? __ldg(&d_csr[it1]) : 0;
        float4 v = __ldg(&((const float4*)d_h1p)[(size_t)s * 4 + p]);
        acc.x += v.x; acc.y += v.y; acc.z += v.z; acc.w += v.w;
        s = s1; it = it1; ok = ok1;
    }
    __syncwarp();
    #pragma unroll
    for (int off = 16; off >= 4; off >>= 1) {
        acc.x += __shfl_down_sync(0xffffffffu, acc.x, off);
        acc.y += __shfl_down_sync(0xffffffffu, acc.y, off);
        acc.z += __shfl_down_sync(0xffffffffu, acc.z, off);
        acc.w += __shfl_down_sync(0xffffffffu, acc.w, off);
    }
    if (lane < 4) {
        float dv = d_dinv[warp];
        float4 self = ((const float4*)d_h1p)[warp * 4 + lane];
        acc.x += self.x; acc.y += self.y; acc.z += self.z; acc.w += self.w;
        float4 bb = __ldg(&((const float4*)b1)[lane]);
        float4 w  = __ldg(&((const float4*)W2)[lane]);
        float g = fmaxf(fmaf(dv, acc.x, bb.x), 0.f) * w.x
                + fmaxf(fmaf(dv, acc.y, bb.y), 0.f) * w.y
                + fmaxf(fmaf(dv, acc.z, bb.z), 0.f) * w.z
                + fmaxf(fmaf(dv, acc.w, bb.w), 0.f) * w.w;
        g += __shfl_xor_sync(0xfu, g, 1);
        g += __shfl_xor_sync(0xfu, g, 2);
        if (lane == 0) d_gp[warp] = g * dv;
    }
}

// Layer-2 aggregation + sigmoid. One warp per node, gather-only.
__global__ void __launch_bounds__(256) k_agg2(const float* __restrict__ b2,
                                              float* __restrict__ out, int N) {
    int warp = (blockIdx.x * blockDim.x + threadIdx.x) >> 5;
    if (warp >= N) return;
    int lane = threadIdx.x & 31;
    int base = __ldg(&d_rs[warp]);
    int end  = __ldg(&d_rs[warp + 1]);

    float sum = 0.f;
    for (int j = base + lane; j < end; j += 32)
        sum += __ldg(&d_gp[__ldg(&d_csr[j])]);
    __syncwarp();
    #pragma unroll
    for (int off = 16; off >= 1; off >>= 1)
        sum += __shfl_down_sync(0xffffffffu, sum, off);
    if (lane == 0) {
        float dv = d_dinv[warp];
        float z = fmaf(dv, sum + d_gp[warp], __ldg(&b2[0]));
        out[warp] = 1.f / (1.f + __expf(-z));
    }
}

// ---------------- launch (7 kernels, single stream) ----------------
extern "C" void kernel_launch(void* const* d_in, const int* in_sizes, int n_in,
                              void* d_out, int out_size) {
    const float* x  = (const float*)d_in[0];
    const float* W1 = (const float*)d_in[1];
    const float* b1 = (const float*)d_in[2];
    const float* W2 = (const float*)d_in[3];
    const float* b2 = (const float*)d_in[4];
    const int*   ei = (const int*)d_in[5];

    int N = in_sizes[0] / FIN;     // 100000
    int E = in_sizes[5] / 2;       // 3200000
    int NB = (N + SCAN_BS - 1) / SCAN_BS;

    const int SMEM_BYTES = (FIN * HID + 2 * 8192) * (int)sizeof(float); // 98304
    static bool inited = false;
    if (!inited) {
        cudaFuncSetAttribute(k_gemmA, cudaFuncAttributeMaxDynamicSharedMemorySize,
                             SMEM_BYTES);
        cudaFuncSetAttribute(k_gemmB, cudaFuncAttributeMaxDynamicSharedMemorySize,
                             SMEM_BYTES);
        inited = true;
    }

    int nbA = ROWS_A / 256;                     // 196
    int nbB = (N - ROWS_A + 255) / 256;         // 195

    k_gemmA    <<<nbA, 256, SMEM_BYTES>>>(x, W1, ei + E, N, E);  // gemm(1st half) ∥ deg
    k_scanA    <<<NB, SCAN_BS>>>(N);
    k_scanFix  <<<(N + 255) / 256, 256>>>(N);
    k_gemmB    <<<nbB, 256, SMEM_BYTES>>>(x, W1, ei, N, E);      // 4th: gemm ∥ fill
    k_scaledinv<<<(N * 4 + 255) / 256, 256>>>(N * 4);
    k_agg1     <<<(N * 32 + 255) / 256, 256>>>(b1, W2, N);
    k_agg2     <<<(N * 32 + 255) / 256, 256>>>(b2, (float*)d_out, N);
}

// round 12
// speedup vs baseline: 1.2561x; 1.2561x over previous
#include <cuda_runtime.h>
#include <mma.h>

using namespace nvcuda;

#define NMAX 100000
#define FIN  512
#define HID  16
#define XPAD 36                 // x-tile row pad (floats): 144B, 16B-aligned, ld-conflict-free
#define WPAD 20                 // W row pad (floats): 80B, 16B-aligned, conflict-free b loads

// ---------------- scratch (zero-initialized at module load) ----------------
__device__ float d_deg [NMAX];          // degree excl self-loop (re-zeroed each call)
__device__ float d_dinv[NMAX];          // (deg+1)^-1/2
__device__ float d_h1p [NMAX * HID];    // h1 raw, then h1*dinv after scaledinv
__device__ float d_acc1[NMAX * HID];    // layer-1 accumulator (init = self msg)
__device__ float d_gp  [NMAX];          // g * dinv[row]
__device__ float d_acc2[NMAX];          // layer-2 accumulator

__device__ __forceinline__ unsigned smem_u32(const void* p) {
    unsigned r;
    asm("{ .reg .u64 t; cvta.to.shared.u64 t, %1; cvt.u32.u64 %0, t; }"
        : "=r"(r) : "l"(p));
    return r;
}

// prefetch one 256-row x 32-col x tile (kt) into smem via cp.async.
// dst row stride = XPAD floats (144B). 128 threads x 16 float4.
__device__ __forceinline__ void tile_prefetch(const float* __restrict__ x,
                                              unsigned bufbase, int rbase,
                                              int kt, int tid, int N) {
    #pragma unroll
    for (int i = 0; i < 16; i++) {
        int fid = tid + i * 128;         // 0..2047
        int r = fid >> 3, c4 = fid & 7;
        int gr = rbase + r;
        if (gr < N) {
            const float* g = x + (size_t)gr * FIN + kt * 32 + c4 * 4;
            unsigned d = bufbase + (unsigned)(r * (XPAD * 4) + c4 * 16);
            asm volatile("cp.async.cg.shared.global [%0], [%1], 16;"
                         :: "r"(d), "l"(g));
        }
    }
    asm volatile("cp.async.commit_group;");
}

// Fused: warps 0-3 = tf32 WMMA GEMM (64 rows/warp, 256 rows/block),
//        warps 4-7 = degree histogram (fire-and-forget REDG).
__global__ void __launch_bounds__(256, 2) k_gemmdeg(const float* __restrict__ x,
                                                    const float* __restrict__ W1,
                                                    const int* __restrict__ dst,
                                                    int N, int E) {
    extern __shared__ float sm[];
    float* Ws = sm;                          // 512 x WPAD floats (40KB), tf32-converted
    float* xs = sm + FIN * WPAD;             // 2 x 256 x XPAD floats (72KB)
    int tid = threadIdx.x;

    if (tid >= 128) {                        // ---- degree warps ----
        int dt = tid - 128;
        long long start = (long long)blockIdx.x * E / gridDim.x;
        long long stop  = (long long)(blockIdx.x + 1) * E / gridDim.x;
        for (long long e = start + dt; e < stop; e += 128)
            atomicAdd(&d_deg[dst[e]], 1.0f);
        return;
    }

    // ---- tensor warps ----
    {   // stage W1, converting to tf32 (so b_frag loads need no cvt)
        const float4* W4 = (const float4*)W1;
        #pragma unroll
        for (int i = 0; i < 16; i++) {
            int f = tid + i * 128;           // float4 index, 0..2047
            int row = f >> 2, c4 = f & 3;
            float4 v = W4[f];
            v.x = wmma::__float_to_tf32(v.x);
            v.y = wmma::__float_to_tf32(v.y);
            v.z = wmma::__float_to_tf32(v.z);
            v.w = wmma::__float_to_tf32(v.w);
            *(float4*)(Ws + row * WPAD + c4 * 4) = v;
        }
    }

    int warp = tid >> 5;                     // 0..3
    int wrow = warp * 64;                    // in-block row base for this warp
    int rbase = blockIdx.x * 256;
    unsigned buf0 = smem_u32(xs);

    wmma::fragment<wmma::accumulator, 16, 16, 8, float> c[4];
    #pragma unroll
    for (int t = 0; t < 4; t++) wmma::fill_fragment(c[t], 0.0f);

    tile_prefetch(x, buf0, rbase, 0, tid, N);

    #pragma unroll 1
    for (int kt = 0; kt < 16; kt++) {
        if (kt < 15) {
            tile_prefetch(x, buf0 + ((kt + 1) & 1) * (256 * XPAD * 4),
                          rbase, kt + 1, tid, N);
            asm volatile("cp.async.wait_group 1;");
        } else {
            asm volatile("cp.async.wait_group 0;");
        }
        asm volatile("bar.sync 1, 128;");    // tensor warps only

        const float* xb = xs + (kt & 1) * (256 * XPAD);
        #pragma unroll
        for (int kk = 0; kk < 4; kk++) {
            wmma::fragment<wmma::matrix_b, 16, 16, 8, wmma::precision::tf32,
                           wmma::row_major> b;
            wmma::load_matrix_sync(b, Ws + (kt * 32 + kk * 8) * WPAD, WPAD);
            #pragma unroll
            for (int t = 0; t < 4; t++) {
                wmma::fragment<wmma::matrix_a, 16, 16, 8, wmma::precision::tf32,
                               wmma::row_major> a;
                wmma::load_matrix_sync(a, xb + (wrow + t * 16) * XPAD + kk * 8,
                                       XPAD);
                #pragma unroll
                for (int i = 0; i < a.num_elements; i++)
                    a.x[i] = wmma::__float_to_tf32(a.x[i]);
                wmma::mma_sync(c[t], a, b, c[t]);
            }
        }
        asm volatile("bar.sync 1, 128;");
    }

    // epilogue: store raw h1 (N is a multiple of 16 -> whole tiles valid/invalid)
    #pragma unroll
    for (int t = 0; t < 4; t++) {
        int r0 = rbase + wrow + t * 16;
        if (r0 < N)
            wmma::store_matrix_sync(d_h1p + (size_t)r0 * HID, c[t], HID,
                                    wmma::mem_row_major);
    }
}

// dinv = rsqrt(deg+1); h1p *= dinv; acc1 = h1p (self-loop init); deg re-zeroed.
__global__ void k_scaledinv(int N4) {
    int t = blockIdx.x * blockDim.x + threadIdx.x;
    if (t >= N4) return;
    int row = t >> 2;
    float dv = rsqrtf(d_deg[row] + 1.0f);
    if ((t & 3) == 0) {
        d_dinv[row] = dv;
        d_deg[row]  = 0.0f;              // ready for next replay
    }
    float4 v = ((float4*)d_h1p)[t];
    v.x *= dv; v.y *= dv; v.z *= dv; v.w *= dv;
    ((float4*)d_h1p)[t]  = v;
    ((float4*)d_acc1)[t] = v;
}

// Layer-1 edge pass: acc1[dst] += h1p[src]. 4 lanes/edge, red.v4.
__global__ void k_edge1(const int* __restrict__ ei, int E) {
    int t = blockIdx.x * blockDim.x + threadIdx.x;
    int e = t >> 2, p = t & 3;
    if (e >= E) return;
    int s = ei[e];
    int d = ei[E + e];
    float4 v = __ldg(&((const float4*)d_h1p)[(size_t)s * 4 + p]);
    float* op = d_acc1 + (size_t)d * HID + p * 4;
    asm volatile("red.global.add.v4.f32 [%0],{%1,%2,%3,%4};"
                 :: "l"(op), "f"(v.x), "f"(v.y), "f"(v.z), "f"(v.w) : "memory");
}

// Per-node: h = relu(dinv*acc1 + b1); g = h.W2; gp = g*dinv; acc2 init.
__global__ void k_layer2(const float* __restrict__ b1,
                         const float* __restrict__ W2, int N) {
    int i = blockIdx.x * blockDim.x + threadIdx.x;
    if (i >= N) return;
    float dv = d_dinv[i];
    const float4* ap = (const float4*)(d_acc1 + (size_t)i * HID);
    float g = 0.f;
    #pragma unroll
    for (int q = 0; q < 4; q++) {
        float4 a  = ap[q];
        float4 bb = __ldg(&((const float4*)b1)[q]);
        float4 w  = __ldg(&((const float4*)W2)[q]);
        g += fmaxf(fmaf(dv, a.x, bb.x), 0.f) * w.x;
        g += fmaxf(fmaf(dv, a.y, bb.y), 0.f) * w.y;
        g += fmaxf(fmaf(dv, a.z, bb.z), 0.f) * w.z;
        g += fmaxf(fmaf(dv, a.w, bb.w), 0.f) * w.w;
    }
    float gp = g * dv;
    d_gp[i]   = gp;
    d_acc2[i] = gp;   // self-loop term
}

// Layer-2 edge pass: acc2[dst] += gp[src].
__global__ void k_edge2(const int* __restrict__ ei, int E) {
    int e = blockIdx.x * blockDim.x + threadIdx.x;
    if (e >= E) return;
    atomicAdd(&d_acc2[ei[E + e]], __ldg(&d_gp[ei[e]]));
}

__global__ void k_sig(const float* __restrict__ b2, float* __restrict__ out, int N) {
    int i = blockIdx.x * blockDim.x + threadIdx.x;
    if (i >= N) return;
    float z = fmaf(d_dinv[i], d_acc2[i], __ldg(&b2[0]));
    out[i] = 1.f / (1.f + __expf(-z));
}

// ---------------- launch (single stream, 6 kernels) ----------------
extern "C" void kernel_launch(void* const* d_in, const int* in_sizes, int n_in,
                              void* d_out, int out_size) {
    const float* x  = (const float*)d_in[0];
    const float* W1 = (const float*)d_in[1];
    const float* b1 = (const float*)d_in[2];
    const float* W2 = (const float*)d_in[3];
    const float* b2 = (const float*)d_in[4];
    const int*   ei = (const int*)d_in[5];

    int N = in_sizes[0] / FIN;     // 100000
    int E = in_sizes[5] / 2;       // 3200000

    // smem: W 512x20 (40KB) + 2 x 256x36 x-tiles (72KB) = 112KB -> 2 CTAs/SM
    const int SMEM_BYTES = (FIN * WPAD + 2 * 256 * XPAD) * (int)sizeof(float);
    static bool inited = false;
    if (!inited) {
        cudaFuncSetAttribute(k_gemmdeg, cudaFuncAttributeMaxDynamicSharedMemorySize,
                             SMEM_BYTES);
        inited = true;
    }

    int nb = (N + 255) / 256;      // 391 blocks
    long long t1 = 4LL * E;

    k_gemmdeg  <<<nb, 256, SMEM_BYTES>>>(x, W1, ei + E, N, E);
    k_scaledinv<<<(N * 4 + 255) / 256, 256>>>(N * 4);
    k_edge1    <<<(unsigned)((t1 + 255) / 256), 256>>>(ei, E);
    k_layer2   <<<(N + 255) / 256, 256>>>(b1, W2, N);
    k_edge2    <<<(E + 255) / 256, 256>>>(ei, E);
    k_sig      <<<(N + 255) / 256, 256>>>(b2, (float*)d_out, N);
}

// round 13
// speedup vs baseline: 1.3789x; 1.0977x over previous
#include <cuda_runtime.h>
#include <cuda_fp16.h>
#include <mma.h>

using namespace nvcuda;

#define NMAX 100000
#define FIN  512
#define HID  16
#define XPAD 36
#define WPAD 20

// ---------------- scratch (zero-initialized at module load) ----------------
__device__ float  d_deg  [NMAX];         // degree excl self-loop (re-zeroed)
__device__ float  d_dinv [NMAX];         // (deg+1)^-1/2
__device__ float  d_h1f  [NMAX * HID];   // raw fp32 h1 from gemm
__device__ __half d_h1h  [NMAX * HID];   // fp16 pre-scaled messages (32B/row)
__device__ __half d_acc1 [NMAX * HID];   // fp16 layer-1 accumulator
__device__ float  d_gp   [NMAX];         // g * dinv[row]
__device__ float  d_acc2 [NMAX];         // layer-2 accumulator (fp32)

__device__ __forceinline__ unsigned smem_u32(const void* p) {
    unsigned r;
    asm("{ .reg .u64 t; cvta.to.shared.u64 t, %1; cvt.u32.u64 %0, t; }"
        : "=r"(r) : "l"(p));
    return r;
}

// prefetch one 256-row x 32-col x tile into smem via cp.async (XPAD stride)
__device__ __forceinline__ void tile_prefetch(const float* __restrict__ x,
                                              unsigned bufbase, int rbase,
                                              int kt, int tid, int N) {
    #pragma unroll
    for (int i = 0; i < 16; i++) {
        int fid = tid + i * 128;
        int r = fid >> 3, c4 = fid & 7;
        int gr = rbase + r;
        if (gr < N) {
            const float* g = x + (size_t)gr * FIN + kt * 32 + c4 * 4;
            unsigned d = bufbase + (unsigned)(r * (XPAD * 4) + c4 * 16);
            asm volatile("cp.async.cg.shared.global [%0], [%1], 16;"
                         :: "r"(d), "l"(g));
        }
    }
    asm volatile("cp.async.commit_group;");
}

// Fused: warps 0-3 = tf32 WMMA GEMM (256 rows/block), warps 4-7 = deg histogram.
__global__ void __launch_bounds__(256, 2) k_gemmdeg(const float* __restrict__ x,
                                                    const float* __restrict__ W1,
                                                    const int* __restrict__ dst,
                                                    int N, int E) {
    extern __shared__ float sm[];
    float* Ws = sm;                          // 512 x WPAD (40KB) tf32
    float* xs = sm + FIN * WPAD;             // 2 x 256 x XPAD (72KB)
    int tid = threadIdx.x;

    if (tid >= 128) {                        // ---- degree warps ----
        int dt = tid - 128;
        long long start = (long long)blockIdx.x * E / gridDim.x;
        long long stop  = (long long)(blockIdx.x + 1) * E / gridDim.x;
        for (long long e = start + dt; e < stop; e += 128)
            atomicAdd(&d_deg[dst[e]], 1.0f);
        return;
    }

    {   // stage W1, tf32-converted
        const float4* W4 = (const float4*)W1;
        #pragma unroll
        for (int i = 0; i < 16; i++) {
            int f = tid + i * 128;
            int row = f >> 2, c4 = f & 3;
            float4 v = W4[f];
            v.x = wmma::__float_to_tf32(v.x);
            v.y = wmma::__float_to_tf32(v.y);
            v.z = wmma::__float_to_tf32(v.z);
            v.w = wmma::__float_to_tf32(v.w);
            *(float4*)(Ws + row * WPAD + c4 * 4) = v;
        }
    }

    int warp = tid >> 5;
    int wrow = warp * 64;
    int rbase = blockIdx.x * 256;
    unsigned buf0 = smem_u32(xs);

    wmma::fragment<wmma::accumulator, 16, 16, 8, float> c[4];
    #pragma unroll
    for (int t = 0; t < 4; t++) wmma::fill_fragment(c[t], 0.0f);

    tile_prefetch(x, buf0, rbase, 0, tid, N);

    #pragma unroll 1
    for (int kt = 0; kt < 16; kt++) {
        if (kt < 15) {
            tile_prefetch(x, buf0 + ((kt + 1) & 1) * (256 * XPAD * 4),
                          rbase, kt + 1, tid, N);
            asm volatile("cp.async.wait_group 1;");
        } else {
            asm volatile("cp.async.wait_group 0;");
        }
        asm volatile("bar.sync 1, 128;");

        const float* xb = xs + (kt & 1) * (256 * XPAD);
        #pragma unroll
        for (int kk = 0; kk < 4; kk++) {
            wmma::fragment<wmma::matrix_b, 16, 16, 8, wmma::precision::tf32,
                           wmma::row_major> b;
            wmma::load_matrix_sync(b, Ws + (kt * 32 + kk * 8) * WPAD, WPAD);
            #pragma unroll
            for (int t = 0; t < 4; t++) {
                wmma::fragment<wmma::matrix_a, 16, 16, 8, wmma::precision::tf32,
                               wmma::row_major> a;
                wmma::load_matrix_sync(a, xb + (wrow + t * 16) * XPAD + kk * 8,
                                       XPAD);
                #pragma unroll
                for (int i = 0; i < a.num_elements; i++)
                    a.x[i] = wmma::__float_to_tf32(a.x[i]);
                wmma::mma_sync(c[t], a, b, c[t]);
            }
        }
        asm volatile("bar.sync 1, 128;");
    }

    #pragma unroll
    for (int t = 0; t < 4; t++) {
        int r0 = rbase + wrow + t * 16;
        if (r0 < N)
            wmma::store_matrix_sync(d_h1f + (size_t)r0 * HID, c[t], HID,
                                    wmma::mem_row_major);
    }
}

// dinv; h1h = half(h1 * dinv); acc1 = h1h (self init); deg re-zeroed.
// One thread per float4 (4 threads/row), 8B half output each.
__global__ void k_scaledinv(int N4) {
    int t = blockIdx.x * blockDim.x + threadIdx.x;
    if (t >= N4) return;
    int row = t >> 2, q = t & 3;
    float dv = rsqrtf(d_deg[row] + 1.0f);
    if (q == 0) {
        d_dinv[row] = dv;
        d_deg[row]  = 0.0f;
    }
    float4 v = ((const float4*)d_h1f)[t];
    __half2 h0 = __floats2half2_rn(v.x * dv, v.y * dv);
    __half2 h1 = __floats2half2_rn(v.z * dv, v.w * dv);
    uint2 u = make_uint2(*(unsigned*)&h0, *(unsigned*)&h1);
    *(uint2*)(d_h1h  + (size_t)row * HID + q * 4) = u;
    *(uint2*)(d_acc1 + (size_t)row * HID + q * 4) = u;
}

// Layer-1 edge pass: acc1[dst] += h1h[src], fp16. 2 lanes/edge, red.v4.f16x2.
__global__ void k_edge1(const int* __restrict__ ei, int E) {
    int t = blockIdx.x * blockDim.x + threadIdx.x;
    int e = t >> 1, p = t & 1;
    if (e >= E) return;
    int s = ei[e];
    int d = ei[E + e];
    uint4 v = __ldg((const uint4*)(d_h1h + (size_t)s * HID + p * 8));
    __half* op = d_acc1 + (size_t)d * HID + p * 8;
    asm volatile("red.global.add.noftz.v4.f16x2 [%0],{%1,%2,%3,%4};"
                 :: "l"(op), "r"(v.x), "r"(v.y), "r"(v.z), "r"(v.w) : "memory");
}

// Per-node: h = relu(dinv*acc1 + b1); g = h.W2; gp = g*dinv; acc2 init.
__global__ void k_layer2(const float* __restrict__ b1,
                         const float* __restrict__ W2, int N) {
    int i = blockIdx.x * blockDim.x + threadIdx.x;
    if (i >= N) return;
    float dv = d_dinv[i];
    const uint4* ap = (const uint4*)(d_acc1 + (size_t)i * HID);
    float g = 0.f;
    #pragma unroll
    for (int q = 0; q < 2; q++) {
        uint4 u = ap[q];
        float2 f0 = __half22float2(*(__half2*)&u.x);
        float2 f1 = __half22float2(*(__half2*)&u.y);
        float2 f2 = __half22float2(*(__half2*)&u.z);
        float2 f3 = __half22float2(*(__half2*)&u.w);
        float4 b0 = __ldg(&((const float4*)b1)[q * 2]);
        float4 b4 = __ldg(&((const float4*)b1)[q * 2 + 1]);
        float4 w0 = __ldg(&((const float4*)W2)[q * 2]);
        float4 w4 = __ldg(&((const float4*)W2)[q * 2 + 1]);
        g += fmaxf(fmaf(dv, f0.x, b0.x), 0.f) * w0.x;
        g += fmaxf(fmaf(dv, f0.y, b0.y), 0.f) * w0.y;
        g += fmaxf(fmaf(dv, f1.x, b0.z), 0.f) * w0.z;
        g += fmaxf(fmaf(dv, f1.y, b0.w), 0.f) * w0.w;
        g += fmaxf(fmaf(dv, f2.x, b4.x), 0.f) * w4.x;
        g += fmaxf(fmaf(dv, f2.y, b4.y), 0.f) * w4.y;
        g += fmaxf(fmaf(dv, f3.x, b4.z), 0.f) * w4.z;
        g += fmaxf(fmaf(dv, f3.y, b4.w), 0.f) * w4.w;
    }
    float gp = g * dv;
    d_gp[i]   = gp;
    d_acc2[i] = gp;   // self-loop term
}

// Layer-2 edge pass: acc2[dst] += gp[src] (fp32 scalar).
__global__ void k_edge2(const int* __restrict__ ei, int E) {
    int e = blockIdx.x * blockDim.x + threadIdx.x;
    if (e >= E) return;
    atomicAdd(&d_acc2[ei[E + e]], __ldg(&d_gp[ei[e]]));
}

__global__ void k_sig(const float* __restrict__ b2, float* __restrict__ out, int N) {
    int i = blockIdx.x * blockDim.x + threadIdx.x;
    if (i >= N) return;
    float z = fmaf(d_dinv[i], d_acc2[i], __ldg(&b2[0]));
    out[i] = 1.f / (1.f + __expf(-z));
}

// ---------------- launch (single stream, 6 kernels) ----------------
extern "C" void kernel_launch(void* const* d_in, const int* in_sizes, int n_in,
                              void* d_out, int out_size) {
    const float* x  = (const float*)d_in[0];
    const float* W1 = (const float*)d_in[1];
    const float* b1 = (const float*)d_in[2];
    const float* W2 = (const float*)d_in[3];
    const float* b2 = (const float*)d_in[4];
    const int*   ei = (const int*)d_in[5];

    int N = in_sizes[0] / FIN;     // 100000
    int E = in_sizes[5] / 2;       // 3200000

    const int SMEM_BYTES = (FIN * WPAD + 2 * 256 * XPAD) * (int)sizeof(float);
    static bool inited = false;
    if (!inited) {
        cudaFuncSetAttribute(k_gemmdeg, cudaFuncAttributeMaxDynamicSharedMemorySize,
                             SMEM_BYTES);
        inited = true;
    }

    int nb = (N + 255) / 256;      // 391 blocks
    long long t1 = 2LL * E;        // 2 lanes per edge now

    k_gemmdeg  <<<nb, 256, SMEM_BYTES>>>(x, W1, ei + E, N, E);
    k_scaledinv<<<(N * 4 + 255) / 256, 256>>>(N * 4);
    k_edge1    <<<(unsigned)((t1 + 255) / 256), 256>>>(ei, E);
    k_layer2   <<<(N + 255) / 256, 256>>>(b1, W2, N);
    k_edge2    <<<(E + 255) / 256, 256>>>(ei, E);
    k_sig      <<<(N + 255) / 256, 256>>>(b2, (float*)d_out, N);
}